// round 6
// baseline (speedup 1.0000x reference)
#include <cuda_runtime.h>
#include <cuda_bf16.h>
#include <mma.h>

using namespace nvcuda;

#define ALPHA   0.2f          // DT/TAU = 20/100
#define NN      2048
#define BB      64
#define TT      200
#define NI      32
#define NO      8
#define G_CTAS  64
#define N_TILE  32            // neurons per CTA (2048/64)
#define LDJ     (NN + 16)     // padded bf16 row for J slice in SMEM
#define LDR     40            // padded fp32 row for rec tile

// ---------------- device scratch (no allocations allowed) ----------------
__device__ float          d_dn[(size_t)TT * BB * NN];          // alpha*(drive+noise), [t][b][n]
__device__ float          d_act_f32[(size_t)(TT + 1) * BB * NN]; // tanh(h_t), [t][b][n]
__device__ __nv_bfloat16  d_act_bf16[(size_t)(TT + 1) * BB * NN];
__device__ unsigned int   g_bar;                                 // grid barrier counter

static const int SMEM_BYTES = N_TILE * LDJ * 2      // J slice bf16
                            + 2 * 64 * LDR * 4      // rec partials (2 K-halves)
                            + BB * N_TILE * 4;      // persistent h slice

// ---------------- pre-pass: dn = alpha * (u @ In_w^T + noise) ----------------
__global__ void dn_kernel(const float* __restrict__ u,
                          const float* __restrict__ In_w,
                          const float* __restrict__ noise) {
    int t  = blockIdx.x;           // 0..199
    int n0 = blockIdx.y * 128;     // 16 chunks of 128 neurons
    __shared__ float us[BB][NI];   // u[:, t, :]
    __shared__ float ws[128][NI];  // In_w chunk
    int tid = threadIdx.x;         // 256 threads

    for (int idx = tid; idx < BB * NI; idx += 256) {
        int b = idx / NI, i = idx % NI;
        us[b][i] = u[((size_t)b * TT + t) * NI + i];
    }
    for (int idx = tid; idx < 128 * NI; idx += 256) {
        int r = idx / NI, i = idx % NI;
        ws[r][i] = In_w[(size_t)(n0 + r) * NI + i];
    }
    __syncthreads();

    int b  = tid >> 2;             // 0..63
    int ns = (tid & 3) * 32;       // 0,32,64,96
    const float* nz  = noise + ((size_t)b * TT + t) * NN + n0 + ns;
    float*       out = d_dn  + ((size_t)t * BB + b) * NN + n0 + ns;
    for (int nn = 0; nn < 32; nn++) {
        float s = 0.f;
        #pragma unroll
        for (int i = 0; i < NI; i++) s += us[b][i] * ws[ns + nn][i];
        out[nn] = ALPHA * (s + nz[nn]);
    }
}

// ---------------- act slot 0 = tanh(h0) broadcast over batch ----------------
__global__ void act0_kernel(const float* __restrict__ h0) {
    int idx = blockIdx.x * 256 + threadIdx.x;   // over BB*NN
    if (idx < BB * NN) {
        int n = idx % NN;
        float th = tanhf(h0[n]);
        d_act_f32[idx]  = th;
        d_act_bf16[idx] = __float2bfloat16(th);
    }
}

// ---------------- persistent recurrent kernel ----------------
extern __shared__ char smem_raw[];

__global__ void __launch_bounds__(512, 1)
rnn_kernel(const float* __restrict__ J, const float* __restrict__ h0) {
    __nv_bfloat16* Jsm = (__nv_bfloat16*)smem_raw;                           // [N_TILE][LDJ]
    float* rec = (float*)(smem_raw + N_TILE * LDJ * sizeof(__nv_bfloat16));  // [2][64][LDR]
    float* hsm = rec + 2 * 64 * LDR;                                         // [64][N_TILE]

    int tid = threadIdx.x;
    int cta = blockIdx.x;
    int u0  = cta * N_TILE;

    // Load + convert this CTA's J slice to bf16 SMEM (stays resident for all steps)
    for (int idx = tid; idx < N_TILE * NN; idx += 512) {
        int r = idx / NN, c = idx % NN;
        Jsm[r * LDJ + c] = __float2bfloat16(J[(size_t)(u0 + r) * NN + c]);
    }
    // Init h slice: h[b][uu] = h0[u0+uu]
    for (int idx = tid; idx < BB * N_TILE; idx += 512) {
        int uu = idx % N_TILE;
        hsm[idx] = h0[u0 + uu];
    }
    __syncthreads();

    int wid    = tid >> 5;
    int warp_m = (wid & 7) >> 1;   // 0..3  (16-row batch block)
    int warp_n = wid & 1;          // 0..1  (16-col neuron block)
    int wk     = wid >> 3;         // 0..1  (K half)
    const int   k0   = wk * (NN / 2);
    const float krec = ALPHA / (float)NN;

    for (int t = 0; t < TT; t++) {
        // rec[b][uu] = sum_v act[t][b][v] * Jsm[uu][v]
        wmma::fragment<wmma::accumulator, 16, 16, 16, float> acc;
        wmma::fill_fragment(acc, 0.f);
        const __nv_bfloat16* Abase = d_act_bf16 + (size_t)t * BB * NN + warp_m * 16 * NN;
        const __nv_bfloat16* Bbase = Jsm + warp_n * 16 * LDJ;

        for (int k = k0; k < k0 + NN / 2; k += 16) {
            wmma::fragment<wmma::matrix_a, 16, 16, 16, __nv_bfloat16, wmma::row_major> a;
            wmma::fragment<wmma::matrix_b, 16, 16, 16, __nv_bfloat16, wmma::col_major> b;
            wmma::load_matrix_sync(a, Abase + k, NN);   // act: row-major [b][v]
            wmma::load_matrix_sync(b, Bbase + k, LDJ);  // J:   col-major view of row-major [uu][v]
            wmma::mma_sync(acc, a, b, acc);
        }
        wmma::store_matrix_sync(rec + wk * 64 * LDR + warp_m * 16 * LDR + warp_n * 16,
                                acc, LDR, wmma::mem_row_major);
        __syncthreads();

        // fused h update + tanh + activation stores (fp32 for output GEMM, bf16 for recurrence)
        {
            int b  = tid >> 3;           // 0..63
            int us = (tid & 7) * 4;      // 0..28
            const float*   dnp = d_dn      + ((size_t)t * BB + b) * NN + u0 + us;
            float*         af  = d_act_f32 + ((size_t)(t + 1) * BB + b) * NN + u0 + us;
            __nv_bfloat16* ab  = d_act_bf16 + ((size_t)(t + 1) * BB + b) * NN + u0 + us;
            #pragma unroll
            for (int j = 0; j < 4; j++) {
                int uu  = us + j;
                float r = rec[b * LDR + uu] + rec[64 * LDR + b * LDR + uu];
                float h = hsm[b * N_TILE + uu];
                float hn = (1.f - ALPHA) * h + krec * r + dnp[j];
                hsm[b * N_TILE + uu] = hn;
                float th = tanhf(hn);
                af[j] = th;
                ab[j] = __float2bfloat16(th);
            }
        }
        __syncthreads();   // also protects rec SMEM before next store

        // ---- grid barrier (monotonic counter; reset by follow-up kernel) ----
        if (tid == 0) {
            __threadfence();
            atomicAdd(&g_bar, 1u);
            unsigned target = (unsigned)(t + 1) * G_CTAS;
            unsigned v;
            do {
                asm volatile("ld.acquire.gpu.u32 %0, [%1];" : "=r"(v) : "l"(&g_bar) : "memory");
            } while (v < target);
        }
        __syncthreads();
    }
}

// ---------------- barrier reset so graph replays are deterministic ----------------
__global__ void reset_kernel() { g_bar = 0; }

// ---------------- post-pass: y[b,t,o] = (1/N) sum_n Out[n,o] * tanh(h_t[b,n]) ----------------
__global__ void out_kernel(const float* __restrict__ Out_w, float* __restrict__ y) {
    int t   = blockIdx.x;        // 0..200
    int tid = threadIdx.x;       // 512
    int b   = tid >> 3;          // 0..63
    int s   = tid & 7;           // K-stripe 0..7 (256 n each)
    __shared__ float ps[BB][8][NO];

    float acc[NO];
    #pragma unroll
    for (int o = 0; o < NO; o++) acc[o] = 0.f;

    const float* ap = d_act_f32 + ((size_t)t * BB + b) * NN + s * 256;
    for (int n = 0; n < 256; n++) {
        float a = ap[n];
        const float* w = Out_w + (size_t)(s * 256 + n) * NO;
        #pragma unroll
        for (int o = 0; o < NO; o++) acc[o] += a * w[o];
    }
    #pragma unroll
    for (int o = 0; o < NO; o++) ps[b][s][o] = acc[o];
    __syncthreads();

    if (tid < BB * NO) {
        int bb = tid / NO, o = tid % NO;
        float ssum = 0.f;
        #pragma unroll
        for (int k = 0; k < 8; k++) ssum += ps[bb][k][o];
        y[((size_t)bb * (TT + 1) + t) * NO + o] = ssum / (float)NN;
    }
}

// ---------------- launcher ----------------
extern "C" void kernel_launch(void* const* d_in, const int* in_sizes, int n_in,
                              void* d_out, int out_size) {
    const float* u      = (const float*)d_in[0];
    const float* In_w   = (const float*)d_in[1];
    const float* Out_w  = (const float*)d_in[2];
    const float* J      = (const float*)d_in[3];
    const float* h0     = (const float*)d_in[4];
    const float* noise  = (const float*)d_in[5];
    float*       y      = (float*)d_out;

    cudaFuncSetAttribute(rnn_kernel, cudaFuncAttributeMaxDynamicSharedMemorySize, SMEM_BYTES);

    dim3 gdn(TT, 16);
    dn_kernel<<<gdn, 256>>>(u, In_w, noise);
    act0_kernel<<<(BB * NN + 255) / 256, 256>>>(h0);
    rnn_kernel<<<G_CTAS, 512, SMEM_BYTES>>>(J, h0);
    reset_kernel<<<1, 1>>>();
    out_kernel<<<TT + 1, 512>>>(Out_w, y);
}

// round 7
// speedup vs baseline: 1.5434x; 1.5434x over previous
#include <cuda_runtime.h>
#include <cuda_bf16.h>
#include <mma.h>

using namespace nvcuda;

#define ALPHA   0.2f          // DT/TAU = 20/100
#define NN      2048
#define BB      64
#define TT      200
#define NI      32
#define NO      8
#define G_CTAS  64
#define N_TILE  32            // neurons per CTA
#define LDJ     2056          // padded bf16 row for J slice in SMEM (16B-aligned rows)
#define LDA     264           // padded bf16 row for act chunk in SMEM
#define LDR     36            // padded fp32 row for rec tile
#define CHUNK   256           // K chunk (neurons per staged act chunk)
#define NCHUNK  8

// ---------------- device scratch ----------------
__device__ float          d_dn[(size_t)TT * BB * NN];             // alpha*(drive+noise)
__device__ float          d_act_f32[(size_t)(TT + 1) * BB * NN];  // tanh(h_t) fp32 (for output GEMM)
__device__ __nv_bfloat16  d_act_bf16[(size_t)(TT + 1) * BB * NN]; // tanh(h_t) bf16 (for recurrence)
__device__ unsigned int   d_flags[(TT + 1) * NCHUNK];             // per-(t,chunk) producer counters

static const int SMEM_BYTES = N_TILE * LDJ * 2      // J slice bf16        131584
                            + 2 * BB * LDA * 2      // act double buffer    67584
                            + 2 * BB * LDR * 4      // rec partials         18432
                            + BB * N_TILE * 4;      // persistent h slice    8192  => 225792

__device__ __forceinline__ unsigned ld_acquire_gpu(const unsigned* p) {
    unsigned v;
    asm volatile("ld.acquire.gpu.u32 %0, [%1];" : "=r"(v) : "l"(p) : "memory");
    return v;
}
__device__ __forceinline__ void cp_async16(void* dst_smem, const void* src_gmem) {
    unsigned s = (unsigned)__cvta_generic_to_shared(dst_smem);
    asm volatile("cp.async.ca.shared.global [%0], [%1], 16;" :: "r"(s), "l"(src_gmem) : "memory");
}

// ---------------- prep: dn = alpha*(u@In_w^T + noise); act slot 0; flag init ----------------
__global__ void prep_kernel(const float* __restrict__ u,
                            const float* __restrict__ In_w,
                            const float* __restrict__ noise,
                            const float* __restrict__ h0) {
    int tid = threadIdx.x;   // 256
    if (blockIdx.y < 16) {
        int t  = blockIdx.x;           // 0..199
        int n0 = blockIdx.y * 128;
        __shared__ float us[BB][NI];
        __shared__ float ws[128][NI];
        for (int idx = tid; idx < BB * NI; idx += 256) {
            int b = idx / NI, i = idx % NI;
            us[b][i] = u[((size_t)b * TT + t) * NI + i];
        }
        for (int idx = tid; idx < 128 * NI; idx += 256) {
            int r = idx / NI, i = idx % NI;
            ws[r][i] = In_w[(size_t)(n0 + r) * NI + i];
        }
        __syncthreads();
        int b  = tid >> 2;
        int ns = (tid & 3) * 32;
        const float* nz  = noise + ((size_t)b * TT + t) * NN + n0 + ns;
        float*       out = d_dn  + ((size_t)t * BB + b) * NN + n0 + ns;
        for (int nn = 0; nn < 32; nn++) {
            float s = 0.f;
            #pragma unroll
            for (int i = 0; i < NI; i++) s += us[b][i] * ws[ns + nn][i];
            out[nn] = ALPHA * (s + nz[nn]);
        }
    } else {
        // act slot 0 = tanh(h0) broadcast over batch: 131072 elems over 200 blocks
        int base = blockIdx.x * 656;
        int end  = base + 656; if (end > BB * NN) end = BB * NN;
        for (int i = base + tid; i < end; i += 256) {
            int n = i % NN;
            float th = tanhf(h0[n]);
            d_act_f32[i]  = th;
            d_act_bf16[i] = __float2bfloat16(th);
        }
        if (blockIdx.x == 0) {
            for (int i = tid; i < (TT + 1) * NCHUNK; i += 256)
                d_flags[i] = (i < NCHUNK) ? 8u : 0u;   // slot 0 pre-complete
        }
    }
}

// ---------------- persistent recurrent kernel (+ fused output projection tail) ----------------
extern __shared__ char smem_raw[];

__global__ void __launch_bounds__(512, 1)
rnn_kernel(const float* __restrict__ J, const float* __restrict__ h0,
           const float* __restrict__ Out_w, float* __restrict__ y) {
    __nv_bfloat16* Jsm  = (__nv_bfloat16*)smem_raw;
    __nv_bfloat16* abuf = (__nv_bfloat16*)(smem_raw + N_TILE * LDJ * 2);
    float* rec = (float*)(smem_raw + N_TILE * LDJ * 2 + 2 * BB * LDA * 2);
    float* hsm = rec + 2 * BB * LDR;

    const int tid = threadIdx.x;
    const int cta = blockIdx.x;
    const int u0  = cta * N_TILE;

    // J slice -> bf16 SMEM (resident all steps)
    for (int idx = tid; idx < N_TILE * (NN / 4); idx += 512) {
        int r = idx / (NN / 4), c4 = idx % (NN / 4);
        float4 v = *(const float4*)(J + (size_t)(u0 + r) * NN + c4 * 4);
        __nv_bfloat162 lo = __floats2bfloat162_rn(v.x, v.y);
        __nv_bfloat162 hi = __floats2bfloat162_rn(v.z, v.w);
        *(uint2*)(Jsm + r * LDJ + c4 * 4) = make_uint2(*(unsigned*)&lo, *(unsigned*)&hi);
    }
    for (int idx = tid; idx < BB * N_TILE; idx += 512)
        hsm[idx] = h0[u0 + (idx & (N_TILE - 1))];
    __syncthreads();

    const int wid    = tid >> 5;
    const int warp_m = (wid & 7) >> 1;   // batch 16-row block
    const int warp_n = wid & 1;          // neuron 16-col block
    const int wk     = wid >> 3;         // K half within chunk
    const int c0     = cta >> 3;         // starting chunk rotation (spreads L2 traffic)
    const float krec = ALPHA / (float)NN;

    for (int t = 0; t < TT; t++) {
        // wait for all producers of act[t]
        if (tid < NCHUNK)
            while (ld_acquire_gpu(&d_flags[t * NCHUNK + tid]) < 8u) { }
        __syncthreads();

        const __nv_bfloat16* actg = d_act_bf16 + (size_t)t * BB * NN;

        // prefetch first chunk
        {
            const __nv_bfloat16* src = actg + c0 * CHUNK;
            for (int s = tid; s < 2048; s += 512) {
                int b = s >> 5, o = s & 31;
                cp_async16(abuf + b * LDA + o * 8, src + (size_t)b * NN + o * 8);
            }
            asm volatile("cp.async.commit_group;" ::: "memory");
        }

        wmma::fragment<wmma::accumulator, 16, 16, 16, float> acc;
        wmma::fill_fragment(acc, 0.f);

        for (int i = 0; i < NCHUNK; i++) {
            __syncthreads();  // prior compute done before its buffer is overwritten
            if (i < NCHUNK - 1) {
                int cn = (c0 + i + 1) & 7;
                const __nv_bfloat16* src = actg + cn * CHUNK;
                __nv_bfloat16* dstb = abuf + ((i + 1) & 1) * BB * LDA;
                for (int s = tid; s < 2048; s += 512) {
                    int b = s >> 5, o = s & 31;
                    cp_async16(dstb + b * LDA + o * 8, src + (size_t)b * NN + o * 8);
                }
                asm volatile("cp.async.commit_group;" ::: "memory");
                asm volatile("cp.async.wait_group 1;" ::: "memory");
            } else {
                asm volatile("cp.async.wait_group 0;" ::: "memory");
            }
            __syncthreads();

            const __nv_bfloat16* A = abuf + (i & 1) * BB * LDA + warp_m * 16 * LDA + wk * 128;
            int kg = ((c0 + i) & 7) * CHUNK + wk * 128;
            const __nv_bfloat16* Bp = Jsm + warp_n * 16 * LDJ + kg;
            #pragma unroll
            for (int kk = 0; kk < 8; kk++) {
                wmma::fragment<wmma::matrix_a, 16, 16, 16, __nv_bfloat16, wmma::row_major> af;
                wmma::fragment<wmma::matrix_b, 16, 16, 16, __nv_bfloat16, wmma::col_major> bf;
                wmma::load_matrix_sync(af, A + kk * 16, LDA);
                wmma::load_matrix_sync(bf, Bp + kk * 16, LDJ);
                wmma::mma_sync(acc, af, bf, acc);
            }
        }
        wmma::store_matrix_sync(rec + wk * BB * LDR + warp_m * 16 * LDR + warp_n * 16,
                                acc, LDR, wmma::mem_row_major);
        __syncthreads();

        // fused h update + tanh + act stores (vectorized)
        {
            int b = tid >> 3, us = (tid & 7) * 4;
            float4 r0 = *(float4*)(rec + b * LDR + us);
            float4 r1 = *(float4*)(rec + BB * LDR + b * LDR + us);
            float4 h  = *(float4*)(hsm + b * N_TILE + us);
            float4 dn = *(const float4*)(d_dn + ((size_t)t * BB + b) * NN + u0 + us);
            float4 hn;
            hn.x = (1.f - ALPHA) * h.x + krec * (r0.x + r1.x) + dn.x;
            hn.y = (1.f - ALPHA) * h.y + krec * (r0.y + r1.y) + dn.y;
            hn.z = (1.f - ALPHA) * h.z + krec * (r0.z + r1.z) + dn.z;
            hn.w = (1.f - ALPHA) * h.w + krec * (r0.w + r1.w) + dn.w;
            *(float4*)(hsm + b * N_TILE + us) = hn;
            float4 th;
            th.x = tanhf(hn.x); th.y = tanhf(hn.y); th.z = tanhf(hn.z); th.w = tanhf(hn.w);
            size_t off = ((size_t)(t + 1) * BB + b) * NN + u0 + us;
            *(float4*)(d_act_f32 + off) = th;
            __nv_bfloat162 lo = __floats2bfloat162_rn(th.x, th.y);
            __nv_bfloat162 hi = __floats2bfloat162_rn(th.z, th.w);
            *(uint2*)(d_act_bf16 + off) = make_uint2(*(unsigned*)&lo, *(unsigned*)&hi);
        }
        __syncthreads();
        if (tid == 0) {
            __threadfence();
            atomicAdd(&d_flags[(t + 1) * NCHUNK + c0], 1u);
        }
    }

    // ---- output projection tail: y[b,t,o] = (1/N) sum_n Out[n,o]*tanh(h_t[b,n]) ----
    float* ps = rec;  // reuse as [64][8][8]
    for (int t = cta; t <= TT; t += G_CTAS) {
        if (tid < NCHUNK)
            while (ld_acquire_gpu(&d_flags[t * NCHUNK + tid]) < 8u) { }
        __syncthreads();
        int b = tid >> 3, s = tid & 7;
        float a0 = 0, a1 = 0, a2 = 0, a3 = 0, a4 = 0, a5 = 0, a6 = 0, a7 = 0;
        const float* ap = d_act_f32 + ((size_t)t * BB + b) * NN + s * 256;
        for (int n = 0; n < 256; n++) {
            float a = ap[n];
            const float4* w = (const float4*)(Out_w + (size_t)(s * 256 + n) * NO);
            float4 w0 = w[0], w1 = w[1];
            a0 += a * w0.x; a1 += a * w0.y; a2 += a * w0.z; a3 += a * w0.w;
            a4 += a * w1.x; a5 += a * w1.y; a6 += a * w1.z; a7 += a * w1.w;
        }
        float* pp = ps + (b * 8 + s) * 8;
        pp[0] = a0; pp[1] = a1; pp[2] = a2; pp[3] = a3;
        pp[4] = a4; pp[5] = a5; pp[6] = a6; pp[7] = a7;
        __syncthreads();
        if (tid < BB * NO) {
            int bb = tid / NO, o = tid % NO;
            float ssum = 0.f;
            #pragma unroll
            for (int k = 0; k < 8; k++) ssum += ps[(bb * 8 + k) * 8 + o];
            y[((size_t)bb * (TT + 1) + t) * NO + o] = ssum / (float)NN;
        }
        __syncthreads();
    }
}

// ---------------- launcher (2 kernels: ncu -s 5 -c 1 lands on rnn_kernel) ----------------
extern "C" void kernel_launch(void* const* d_in, const int* in_sizes, int n_in,
                              void* d_out, int out_size) {
    const float* u     = (const float*)d_in[0];
    const float* In_w  = (const float*)d_in[1];
    const float* Out_w = (const float*)d_in[2];
    const float* J     = (const float*)d_in[3];
    const float* h0    = (const float*)d_in[4];
    const float* noise = (const float*)d_in[5];
    float*       y     = (float*)d_out;

    cudaFuncSetAttribute(rnn_kernel, cudaFuncAttributeMaxDynamicSharedMemorySize, SMEM_BYTES);

    dim3 gprep(TT, 17);
    prep_kernel<<<gprep, 256>>>(u, In_w, noise, h0);
    rnn_kernel<<<G_CTAS, 512, SMEM_BYTES>>>(J, h0, Out_w, y);
}